// round 2
// baseline (speedup 1.0000x reference)
#include <cuda_runtime.h>
#include <cuda_bf16.h>

#define FEAT 1024
#define NREF 4
#define WPB 8            // warps (rows) per block
#define TPB (WPB * 32)

// Normalized reflection vectors (16 KB scratch; __device__ global per harness rules)
__device__ float g_vn[NREF * FEAT];

// One warp per vector: sum of squares -> shfl reduce -> scale.
__global__ void normalize_vectors_kernel(const float* __restrict__ v) {
    int w = threadIdx.x >> 5;
    int lane = threadIdx.x & 31;
    if (w >= NREF) return;
    const float* src = v + w * FEAT;
    float ss = 0.f;
#pragma unroll
    for (int j = 0; j < FEAT / 32; j++) {
        float val = src[j * 32 + lane];
        ss = fmaf(val, val, ss);
    }
#pragma unroll
    for (int o = 16; o; o >>= 1) ss += __shfl_xor_sync(0xffffffffu, ss, o);
    float inv = rsqrtf(ss);
#pragma unroll
    for (int j = 0; j < FEAT / 32; j++) {
        g_vn[w * FEAT + j * 32 + lane] = src[j * 32 + lane] * inv;
    }
}

// Warp-per-row: y <- y - 2*(y.v)v, 4 times, all in registers.
__global__ __launch_bounds__(TPB) void householder_apply_kernel(
    const float* __restrict__ x, float* __restrict__ out, int batch) {
    __shared__ float sv[NREF][FEAT];
    // Stage normalized vectors to shared (vectorized)
    {
        const float4* src = (const float4*)g_vn;
        float4* dst = (float4*)sv;
        for (int i = threadIdx.x; i < NREF * FEAT / 4; i += blockDim.x)
            dst[i] = src[i];
    }
    __syncthreads();

    int warp = threadIdx.x >> 5;
    int lane = threadIdx.x & 31;
    long long row = (long long)blockIdx.x * WPB + warp;
    if (row >= batch) return;

    const float4* xr = (const float4*)(x + row * (long long)FEAT);
    float4 y[8];
#pragma unroll
    for (int j = 0; j < 8; j++) y[j] = xr[j * 32 + lane];

#pragma unroll
    for (int k = 0; k < NREF; k++) {
        const float4* vp = (const float4*)sv[k];
        float4 vv[8];
        float dot = 0.f;
#pragma unroll
        for (int j = 0; j < 8; j++) {
            vv[j] = vp[j * 32 + lane];
            dot = fmaf(y[j].x, vv[j].x, dot);
            dot = fmaf(y[j].y, vv[j].y, dot);
            dot = fmaf(y[j].z, vv[j].z, dot);
            dot = fmaf(y[j].w, vv[j].w, dot);
        }
#pragma unroll
        for (int o = 16; o; o >>= 1) dot += __shfl_xor_sync(0xffffffffu, dot, o);
        float s = -2.f * dot;
#pragma unroll
        for (int j = 0; j < 8; j++) {
            y[j].x = fmaf(s, vv[j].x, y[j].x);
            y[j].y = fmaf(s, vv[j].y, y[j].y);
            y[j].z = fmaf(s, vv[j].z, y[j].z);
            y[j].w = fmaf(s, vv[j].w, y[j].w);
        }
    }

    float4* o = (float4*)(out + row * (long long)FEAT);
#pragma unroll
    for (int j = 0; j < 8; j++) o[j * 32 + lane] = y[j];
}

extern "C" void kernel_launch(void* const* d_in, const int* in_sizes, int n_in,
                              void* d_out, int out_size) {
    const float* x = (const float*)d_in[0];       // (BATCH, 1024) fp32
    const float* vectors = (const float*)d_in[1]; // (4, 1024) fp32
    float* out = (float*)d_out;
    int batch = in_sizes[0] / FEAT;

    normalize_vectors_kernel<<<1, NREF * 32>>>(vectors);
    int blocks = (batch + WPB - 1) / WPB;
    householder_apply_kernel<<<blocks, TPB>>>(x, out, batch);
}

// round 8
// speedup vs baseline: 1.0337x; 1.0337x over previous
#include <cuda_runtime.h>
#include <cuda_bf16.h>

#define FEAT 1024
#define NREF 4
#define WPB 8            // warps per block
#define RPW 2            // rows per warp
#define TPB (WPB * 32)
#define ROWS_PER_BLOCK (WPB * RPW)

// Normalized reflection vectors (16 KB scratch; __device__ global per harness rules)
__device__ float g_vn[NREF * FEAT];

// One warp per vector: sum of squares -> shfl reduce -> scale.
__global__ void normalize_vectors_kernel(const float* __restrict__ v) {
    int w = threadIdx.x >> 5;
    int lane = threadIdx.x & 31;
    if (w >= NREF) return;
    const float* src = v + w * FEAT;
    float ss = 0.f;
#pragma unroll
    for (int j = 0; j < FEAT / 32; j++) {
        float val = src[j * 32 + lane];
        ss = fmaf(val, val, ss);
    }
#pragma unroll
    for (int o = 16; o; o >>= 1) ss += __shfl_xor_sync(0xffffffffu, ss, o);
    float inv = rsqrtf(ss);
#pragma unroll
    for (int j = 0; j < FEAT / 32; j++) {
        g_vn[w * FEAT + j * 32 + lane] = src[j * 32 + lane] * inv;
    }
}

// Warp processes TWO rows; the two shfl-reduce chains interleave (latency overlap)
// and the v registers are shared between rows.
__global__ __launch_bounds__(TPB, 2) void householder_apply_kernel(
    const float* __restrict__ x, float* __restrict__ out, int batch) {
    __shared__ float sv[NREF][FEAT];
    {
        const float4* src = (const float4*)g_vn;
        float4* dst = (float4*)sv;
        for (int i = threadIdx.x; i < NREF * FEAT / 4; i += blockDim.x)
            dst[i] = src[i];
    }
    __syncthreads();

    int warp = threadIdx.x >> 5;
    int lane = threadIdx.x & 31;
    long long rowA = (long long)blockIdx.x * ROWS_PER_BLOCK + warp;
    long long rowB = rowA + WPB;
    bool hasA = rowA < batch;
    bool hasB = rowB < batch;

    const float4* xa = (const float4*)(x + rowA * (long long)FEAT);
    const float4* xb = (const float4*)(x + rowB * (long long)FEAT);
    float4 ya[8], yb[8];
    if (hasA) {
#pragma unroll
        for (int j = 0; j < 8; j++) ya[j] = __ldcs(&xa[j * 32 + lane]);
    }
    if (hasB) {
#pragma unroll
        for (int j = 0; j < 8; j++) yb[j] = __ldcs(&xb[j * 32 + lane]);
    }

#pragma unroll
    for (int k = 0; k < NREF; k++) {
        const float4* vp = (const float4*)sv[k];
        float4 vv[8];
        float da = 0.f, db = 0.f;
#pragma unroll
        for (int j = 0; j < 8; j++) {
            vv[j] = vp[j * 32 + lane];
            da = fmaf(ya[j].x, vv[j].x, da);
            da = fmaf(ya[j].y, vv[j].y, da);
            da = fmaf(ya[j].z, vv[j].z, da);
            da = fmaf(ya[j].w, vv[j].w, da);
            db = fmaf(yb[j].x, vv[j].x, db);
            db = fmaf(yb[j].y, vv[j].y, db);
            db = fmaf(yb[j].z, vv[j].z, db);
            db = fmaf(yb[j].w, vv[j].w, db);
        }
        // Two independent butterflies, interleaved so latencies overlap.
#pragma unroll
        for (int o = 16; o; o >>= 1) {
            da += __shfl_xor_sync(0xffffffffu, da, o);
            db += __shfl_xor_sync(0xffffffffu, db, o);
        }
        float sa = -2.f * da;
        float sb = -2.f * db;
#pragma unroll
        for (int j = 0; j < 8; j++) {
            ya[j].x = fmaf(sa, vv[j].x, ya[j].x);
            ya[j].y = fmaf(sa, vv[j].y, ya[j].y);
            ya[j].z = fmaf(sa, vv[j].z, ya[j].z);
            ya[j].w = fmaf(sa, vv[j].w, ya[j].w);
            yb[j].x = fmaf(sb, vv[j].x, yb[j].x);
            yb[j].y = fmaf(sb, vv[j].y, yb[j].y);
            yb[j].z = fmaf(sb, vv[j].z, yb[j].z);
            yb[j].w = fmaf(sb, vv[j].w, yb[j].w);
        }
    }

    if (hasA) {
        float4* oa = (float4*)(out + rowA * (long long)FEAT);
#pragma unroll
        for (int j = 0; j < 8; j++) __stcs(&oa[j * 32 + lane], ya[j]);
    }
    if (hasB) {
        float4* ob = (float4*)(out + rowB * (long long)FEAT);
#pragma unroll
        for (int j = 0; j < 8; j++) __stcs(&ob[j * 32 + lane], yb[j]);
    }
}

extern "C" void kernel_launch(void* const* d_in, const int* in_sizes, int n_in,
                              void* d_out, int out_size) {
    const float* x = (const float*)d_in[0];       // (BATCH, 1024) fp32
    const float* vectors = (const float*)d_in[1]; // (4, 1024) fp32
    float* out = (float*)d_out;
    int batch = in_sizes[0] / FEAT;

    normalize_vectors_kernel<<<1, NREF * 32>>>(vectors);
    int blocks = (batch + ROWS_PER_BLOCK - 1) / ROWS_PER_BLOCK;
    householder_apply_kernel<<<blocks, TPB>>>(x, out, batch);
}